// round 1
// baseline (speedup 1.0000x reference)
#include <cuda_runtime.h>

// ---------------------------------------------------------------------------
// KPConvSimpleBlock: ball query -> KPConv (wf = w^T nf, out = wf @ W) -> BN -> LeakyReLU
// Shapes: B=8, N=4096 (M=32768 points), C_IN=64, C_OUT=128, K=15, MAX_NN=34
// ---------------------------------------------------------------------------

#define MTOT  32768
#define NPER  4096
#define CIN   64
#define COUT  128
#define KPN   15
#define MAXNN 34
#define KC    960          // KPN * CIN

// Effective influence radius: |kp| <= 0.042, w>0 needs dist<0.04 -> reach 0.082.
// Any neighbor beyond that contributes exactly 0 in the reference, so we only
// need neighbors within 0.0826 (margin), capped at 34 (overflow prob ~1e-9).
#define TH2   (0.082f * 0.082f + 1.0e-4f)

// -------------------- device scratch (no allocations allowed) --------------
__device__ int   g_nbr[MTOT * MAXNN];
__device__ int   g_cnt[MTOT];
__device__ float g_wf[MTOT * KC];      // per-point per-kernel-point features
__device__ float g_o [MTOT * COUT];    // pre-BN conv output
__device__ float g_ps[128 * COUT];     // partial sums   [block][chan]
__device__ float g_pq[128 * COUT];     // partial sumsq  [block][chan]
__device__ float g_scale[COUT];
__device__ float g_bias [COUT];

// -------------------- 1. ball query (brute force, smem-tiled) --------------
// grid: 8 clouds * 32 chunks = 256 blocks, 128 threads; thread = one query pt
__global__ void __launch_bounds__(128) ball_query_kernel(const float* __restrict__ xyz)
{
    int b     = blockIdx.x >> 5;
    int chunk = blockIdx.x & 31;
    int t     = threadIdx.x;
    int q     = b * NPER + chunk * 128 + t;

    float qx = xyz[3 * q + 0];
    float qy = xyz[3 * q + 1];
    float qz = xyz[3 * q + 2];

    __shared__ float4 cand[128];

    int  cnt   = 0;
    int* myNbr = g_nbr + q * MAXNN;

    for (int tile = 0; tile < NPER / 128; tile++) {
        int j = b * NPER + tile * 128 + t;
        float4 c4 = make_float4(xyz[3 * j + 0], xyz[3 * j + 1], xyz[3 * j + 2], 0.0f);
        __syncthreads();
        cand[t] = c4;
        __syncthreads();
        int jbase = b * NPER + tile * 128;
        #pragma unroll 4
        for (int jj = 0; jj < 128; jj++) {
            float4 c  = cand[jj];
            float dx = c.x - qx, dy = c.y - qy, dz = c.z - qz;
            float d2 = dx * dx + dy * dy + dz * dz;
            if (d2 <= TH2 && cnt < MAXNN) {
                myNbr[cnt++] = jbase + jj;
            }
        }
    }
    g_cnt[q] = cnt;
}

// -------------------- 2. wf stage: one warp per point -----------------------
// Phase A: cooperatively build w[n][k] table in smem.
// Phase B: lane l accumulates wf[k][l] and wf[k][l+32] over neighbors.
__global__ void __launch_bounds__(128) wf_kernel(const float* __restrict__ xyz,
                                                 const float* __restrict__ feats,
                                                 const float* __restrict__ kpts)
{
    __shared__ float ws[4][MAXNN][16];   // padded to 16 for float4 loads
    __shared__ float kp_s[48];

    int t = threadIdx.x, warp = t >> 5, lane = t & 31;
    if (t < 45) kp_s[t] = kpts[t];

    int m   = blockIdx.x * 4 + warp;
    int cnt = g_cnt[m];
    float mx = xyz[3 * m], my = xyz[3 * m + 1], mz = xyz[3 * m + 2];
    __syncthreads();

    // Phase A: each lane handles neighbors n = lane, lane+32
    for (int n = lane; n < cnt; n += 32) {
        int nb = g_nbr[m * MAXNN + n];
        float rx = xyz[3 * nb]     - mx;
        float ry = xyz[3 * nb + 1] - my;
        float rz = xyz[3 * nb + 2] - mz;
        #pragma unroll
        for (int k = 0; k < KPN; k++) {
            float dx = rx - kp_s[3 * k];
            float dy = ry - kp_s[3 * k + 1];
            float dz = rz - kp_s[3 * k + 2];
            float d  = sqrtf(dx * dx + dy * dy + dz * dz);
            ws[warp][n][k] = fmaxf(1.0f - d * 25.0f, 0.0f);   // 1/KP_EXTENT = 25
        }
    }
    __syncthreads();

    // Phase B
    float acc0[KPN], acc1[KPN];
    #pragma unroll
    for (int k = 0; k < KPN; k++) { acc0[k] = 0.0f; acc1[k] = 0.0f; }

    for (int n = 0; n < cnt; n++) {
        int nb   = g_nbr[m * MAXNN + n];
        float f0 = feats[nb * CIN + lane];
        float f1 = feats[nb * CIN + 32 + lane];
        const float4* wv = (const float4*)ws[warp][n];
        float4 w0 = wv[0], w1 = wv[1], w2 = wv[2], w3 = wv[3];
        acc0[0]  += w0.x * f0;  acc1[0]  += w0.x * f1;
        acc0[1]  += w0.y * f0;  acc1[1]  += w0.y * f1;
        acc0[2]  += w0.z * f0;  acc1[2]  += w0.z * f1;
        acc0[3]  += w0.w * f0;  acc1[3]  += w0.w * f1;
        acc0[4]  += w1.x * f0;  acc1[4]  += w1.x * f1;
        acc0[5]  += w1.y * f0;  acc1[5]  += w1.y * f1;
        acc0[6]  += w1.z * f0;  acc1[6]  += w1.z * f1;
        acc0[7]  += w1.w * f0;  acc1[7]  += w1.w * f1;
        acc0[8]  += w2.x * f0;  acc1[8]  += w2.x * f1;
        acc0[9]  += w2.y * f0;  acc1[9]  += w2.y * f1;
        acc0[10] += w2.z * f0;  acc1[10] += w2.z * f1;
        acc0[11] += w2.w * f0;  acc1[11] += w2.w * f1;
        acc0[12] += w3.x * f0;  acc1[12] += w3.x * f1;
        acc0[13] += w3.y * f0;  acc1[13] += w3.y * f1;
        acc0[14] += w3.z * f0;  acc1[14] += w3.z * f1;
    }

    float* dst = g_wf + m * KC;
    #pragma unroll
    for (int k = 0; k < KPN; k++) {
        dst[k * CIN + lane]      = acc0[k];
        dst[k * CIN + 32 + lane] = acc1[k];
    }
}

// -------------------- 3. GEMM: [32768 x 960] @ [960 x 128] -----------------
// Block tile 128x128, K-chunk 8, 256 threads, 8x8 register tiles.
__global__ void __launch_bounds__(256) gemm_kernel(const float* __restrict__ Wt)
{
    __shared__ float As[8][132];   // A^T, padded
    __shared__ float Bs[8][128];

    int t    = threadIdx.x;
    int rm   = blockIdx.x * 128;
    int trow = (t >> 4) << 3;
    int tcol = (t & 15) << 3;
    int arow = t >> 1;
    int acol = (t & 1) << 2;
    int brow = t >> 5;
    int bcol = (t & 31) << 2;

    const float* Aptr = g_wf + (size_t)(rm + arow) * KC + acol;
    const float* Bptr = Wt + brow * COUT + bcol;

    float acc[8][8];
    #pragma unroll
    for (int i = 0; i < 8; i++)
        #pragma unroll
        for (int j = 0; j < 8; j++) acc[i][j] = 0.0f;

    for (int kc = 0; kc < KC; kc += 8) {
        float4 a  = *(const float4*)(Aptr + kc);
        float4 bv = *(const float4*)(Bptr + kc * COUT);
        __syncthreads();
        As[acol + 0][arow] = a.x;
        As[acol + 1][arow] = a.y;
        As[acol + 2][arow] = a.z;
        As[acol + 3][arow] = a.w;
        *(float4*)&Bs[brow][bcol] = bv;
        __syncthreads();
        #pragma unroll
        for (int k = 0; k < 8; k++) {
            float ar[8], br[8];
            *(float4*)(ar)     = *(const float4*)&As[k][trow];
            *(float4*)(ar + 4) = *(const float4*)&As[k][trow + 4];
            *(float4*)(br)     = *(const float4*)&Bs[k][tcol];
            *(float4*)(br + 4) = *(const float4*)&Bs[k][tcol + 4];
            #pragma unroll
            for (int i = 0; i < 8; i++)
                #pragma unroll
                for (int j = 0; j < 8; j++)
                    acc[i][j] += ar[i] * br[j];
        }
    }

    #pragma unroll
    for (int i = 0; i < 8; i++) {
        float* o = g_o + (size_t)(rm + trow + i) * COUT + tcol;
        *(float4*)(o)     = make_float4(acc[i][0], acc[i][1], acc[i][2], acc[i][3]);
        *(float4*)(o + 4) = make_float4(acc[i][4], acc[i][5], acc[i][6], acc[i][7]);
    }
}

// -------------------- 4. BN stats: deterministic 2-stage reduction ---------
__global__ void __launch_bounds__(256) bn_partial_kernel()
{
    int c    = threadIdx.x & 127;
    int half = threadIdx.x >> 7;
    int base = blockIdx.x * 256 + half * 128;

    float s = 0.0f, q = 0.0f;
    for (int i = 0; i < 128; i++) {
        float v = g_o[(size_t)(base + i) * COUT + c];
        s += v;
        q += v * v;
    }
    __shared__ float sh[256];
    sh[threadIdx.x] = s;
    __syncthreads();
    if (half == 0) g_ps[blockIdx.x * COUT + c] = sh[c] + sh[c + 128];
    __syncthreads();
    sh[threadIdx.x] = q;
    __syncthreads();
    if (half == 0) g_pq[blockIdx.x * COUT + c] = sh[c] + sh[c + 128];
}

__global__ void __launch_bounds__(128) bn_final_kernel(const float* __restrict__ gamma,
                                                       const float* __restrict__ beta)
{
    int c = threadIdx.x;
    float s = 0.0f, q = 0.0f;
    for (int b = 0; b < 128; b++) {
        s += g_ps[b * COUT + c];
        q += g_pq[b * COUT + c];
    }
    const float inv = 1.0f / (float)MTOT;
    float mu  = s * inv;
    float var = q * inv - mu * mu;            // biased var (jnp default)
    float sc  = gamma[c] * rsqrtf(var + 1e-5f);
    g_scale[c] = sc;
    g_bias[c]  = beta[c] - mu * sc;
}

// -------------------- 5. apply BN + LeakyReLU ------------------------------
__global__ void __launch_bounds__(256) bn_apply_kernel(float* __restrict__ out)
{
    int i = blockIdx.x * 256 + threadIdx.x;   // MTOT*COUT / 256 blocks exactly
    int c = i & 127;
    float v = g_o[i] * g_scale[c] + g_bias[c];
    out[i] = (v >= 0.0f) ? v : 0.2f * v;
}

// -------------------- launch -----------------------------------------------
extern "C" void kernel_launch(void* const* d_in, const int* in_sizes, int n_in,
                              void* d_out, int out_size)
{
    const float* xyz    = (const float*)d_in[0];   // [8,4096,3]
    const float* feats  = (const float*)d_in[1];   // [8,4096,64]
    const float* kpts   = (const float*)d_in[2];   // [15,3]
    const float* weight = (const float*)d_in[3];   // [15,64,128] == [960,128]
    const float* gamma  = (const float*)d_in[4];   // [128]
    const float* beta   = (const float*)d_in[5];   // [128]
    float*       out    = (float*)d_out;           // [8,4096,128]

    (void)in_sizes; (void)n_in; (void)out_size;

    ball_query_kernel<<<256, 128>>>(xyz);
    wf_kernel<<<MTOT / 4, 128>>>(xyz, feats, kpts);
    gemm_kernel<<<MTOT / 128, 256>>>(weight);
    bn_partial_kernel<<<128, 256>>>();
    bn_final_kernel<<<1, 128>>>(gamma, beta);
    bn_apply_kernel<<<(MTOT * COUT) / 256, 256>>>(out);
}

// round 3
// speedup vs baseline: 1.5854x; 1.5854x over previous
#include <cuda_runtime.h>
#include <cstdint>

// ---------------------------------------------------------------------------
// KPConvSimpleBlock: ball query -> wf -> mma.sync tf32 GEMM (+fused BN partials)
//                    -> BN finalize -> BN apply + LeakyReLU
// Shapes: B=8, N=4096 (M=32768), C_IN=64, C_OUT=128, K=15, MAX_NN=34
// NOTE: harness compiles for plain sm_103 target -> tcgen05/f32x2 unavailable;
//       use baseline-PTX mma.sync tf32 + cp.async instead.
// ---------------------------------------------------------------------------

#define MTOT  32768
#define NPER  4096
#define CIN   64
#define COUT  128
#define KPN   15
#define MAXNN 34
#define KC    960
#define TH2   (0.082f * 0.082f + 1.0e-4f)

// -------------------- device scratch ---------------------------------------
__device__ float g_wf[MTOT * KC];       // tf32-rounded wf features [M, 960]
__device__ float g_bw[KC * COUT];       // tf32-rounded weight      [960, 128]
__device__ float g_o [MTOT * COUT];
__device__ int   g_nbr[MTOT * MAXNN];
__device__ int   g_cnt[MTOT];
__device__ float g_ps[256 * COUT];
__device__ float g_pq[256 * COUT];
__device__ float g_scale[COUT];
__device__ float g_bias [COUT];

// round-to-nearest fp32 -> tf32 (10 explicit mantissa bits, unbiased)
__device__ __forceinline__ float tf32r(float x) {
    uint32_t u = __float_as_uint(x);
    u = (u + 0x1000u) & 0xFFFFE000u;
    return __uint_as_float(u);
}

__device__ __forceinline__ uint32_t smem_u32(const void* p) {
    uint32_t a;
    asm("{ .reg .u64 t; cvta.to.shared.u64 t, %1; cvt.u32.u64 %0, t; }" : "=r"(a) : "l"(p));
    return a;
}

#define CP_ASYNC16(dst, src) \
    asm volatile("cp.async.cg.shared.global [%0], [%1], 16;" :: "r"(dst), "l"(src) : "memory")
#define CP_COMMIT()   asm volatile("cp.async.commit_group;" ::: "memory")
#define CP_WAIT(n)    asm volatile("cp.async.wait_group %0;" :: "n"(n) : "memory")

// -------------------- 1. ball query ----------------------------------------
__global__ void __launch_bounds__(128) ball_query_kernel(const float* __restrict__ xyz)
{
    int b     = blockIdx.x >> 5;
    int chunk = blockIdx.x & 31;
    int t     = threadIdx.x;
    int q     = b * NPER + chunk * 128 + t;

    float qx = xyz[3 * q + 0], qy = xyz[3 * q + 1], qz = xyz[3 * q + 2];
    __shared__ float4 cand[128];
    int cnt = 0;
    int* myNbr = g_nbr + q * MAXNN;

    for (int tile = 0; tile < NPER / 128; tile++) {
        int j = b * NPER + tile * 128 + t;
        float4 c4 = make_float4(xyz[3 * j], xyz[3 * j + 1], xyz[3 * j + 2], 0.0f);
        __syncthreads();
        cand[t] = c4;
        __syncthreads();
        int jbase = b * NPER + tile * 128;
        #pragma unroll 4
        for (int jj = 0; jj < 128; jj++) {
            float4 c = cand[jj];
            float dx = c.x - qx, dy = c.y - qy, dz = c.z - qz;
            float d2 = dx * dx + dy * dy + dz * dz;
            if (d2 <= TH2 && cnt < MAXNN) myNbr[cnt++] = jbase + jj;
        }
    }
    g_cnt[q] = cnt;
}

// -------------------- 2. wf stage: one warp per point ----------------------
__global__ void __launch_bounds__(128) wf_kernel(const float* __restrict__ xyz,
                                                 const float* __restrict__ feats,
                                                 const float* __restrict__ kpts)
{
    __shared__ float ws[4][MAXNN][16];
    __shared__ float kp_s[48];

    int t = threadIdx.x, warp = t >> 5, lane = t & 31;
    if (t < 45) kp_s[t] = kpts[t];

    int m   = blockIdx.x * 4 + warp;
    int cnt = g_cnt[m];
    float mx = xyz[3 * m], my = xyz[3 * m + 1], mz = xyz[3 * m + 2];
    __syncthreads();

    for (int n = lane; n < cnt; n += 32) {
        int nb = g_nbr[m * MAXNN + n];
        float rx = xyz[3 * nb] - mx, ry = xyz[3 * nb + 1] - my, rz = xyz[3 * nb + 2] - mz;
        #pragma unroll
        for (int k = 0; k < KPN; k++) {
            float dx = rx - kp_s[3 * k], dy = ry - kp_s[3 * k + 1], dz = rz - kp_s[3 * k + 2];
            float d  = sqrtf(dx * dx + dy * dy + dz * dz);
            ws[warp][n][k] = fmaxf(1.0f - d * 25.0f, 0.0f);
        }
    }
    __syncthreads();

    float acc0[KPN], acc1[KPN];
    #pragma unroll
    for (int k = 0; k < KPN; k++) { acc0[k] = 0.0f; acc1[k] = 0.0f; }

    for (int n = 0; n < cnt; n++) {
        int nb   = g_nbr[m * MAXNN + n];
        float f0 = feats[nb * CIN + lane];
        float f1 = feats[nb * CIN + 32 + lane];
        const float4* wv = (const float4*)ws[warp][n];
        float4 w0 = wv[0], w1 = wv[1], w2 = wv[2], w3 = wv[3];
        acc0[0]  += w0.x * f0;  acc1[0]  += w0.x * f1;
        acc0[1]  += w0.y * f0;  acc1[1]  += w0.y * f1;
        acc0[2]  += w0.z * f0;  acc1[2]  += w0.z * f1;
        acc0[3]  += w0.w * f0;  acc1[3]  += w0.w * f1;
        acc0[4]  += w1.x * f0;  acc1[4]  += w1.x * f1;
        acc0[5]  += w1.y * f0;  acc1[5]  += w1.y * f1;
        acc0[6]  += w1.z * f0;  acc1[6]  += w1.z * f1;
        acc0[7]  += w1.w * f0;  acc1[7]  += w1.w * f1;
        acc0[8]  += w2.x * f0;  acc1[8]  += w2.x * f1;
        acc0[9]  += w2.y * f0;  acc1[9]  += w2.y * f1;
        acc0[10] += w2.z * f0;  acc1[10] += w2.z * f1;
        acc0[11] += w2.w * f0;  acc1[11] += w2.w * f1;
        acc0[12] += w3.x * f0;  acc1[12] += w3.x * f1;
        acc0[13] += w3.y * f0;  acc1[13] += w3.y * f1;
        acc0[14] += w3.z * f0;  acc1[14] += w3.z * f1;
    }

    float* dst = g_wf + (size_t)m * KC;
    #pragma unroll
    for (int k = 0; k < KPN; k++) {
        dst[k * CIN + lane]      = tf32r(acc0[k]);
        dst[k * CIN + 32 + lane] = tf32r(acc1[k]);
    }
}

// -------------------- 3. round weight to tf32 (layout already [960,128]) ---
__global__ void __launch_bounds__(256) round_w_kernel(const float* __restrict__ W)
{
    int i = blockIdx.x * 256 + threadIdx.x;   // 480 blocks
    g_bw[i] = tf32r(W[i]);
}

// -------------------- 4. mma.sync tf32 GEMM + fused BN partials ------------
// CTA: 128x128 tile; 4 warps, each 64x64; K-chunks of 32, cp.async double buf.
#define AP      36                      // As row pitch (floats)
#define BP      132                     // Bs row pitch (floats)
#define A_BYTES (128 * AP * 4)          // 18432
#define B_BYTES (32 * BP * 4)           // 16896
#define BUF_BYTES (A_BYTES + B_BYTES)   // 35328
#define GEMM_SMEM (2 * BUF_BYTES)       // 70656 (>= 128*132*4 = 67584 staging)
#define SHP     132                     // staging pitch

__device__ __forceinline__ void issue_chunk(uint32_t abuf, uint32_t bbuf,
                                            const float* __restrict__ Ag,
                                            int c, int t)
{
    // A: 128 rows x 32 k  (1024 float4), 8 per thread
    #pragma unroll
    for (int i = 0; i < 8; i++) {
        int id = i * 128 + t;
        int arow = id >> 3, acol4 = id & 7;
        const float* src = Ag + (size_t)arow * KC + c * 32 + acol4 * 4;
        CP_ASYNC16(abuf + (arow * AP + acol4 * 4) * 4, src);
    }
    // B: 32 k-rows x 128 n (1024 float4), 8 per thread
    #pragma unroll
    for (int i = 0; i < 8; i++) {
        int id = i * 128 + t;
        int krow = id >> 5, n4 = id & 31;
        const float* src = g_bw + (size_t)(c * 32 + krow) * COUT + n4 * 4;
        CP_ASYNC16(bbuf + (krow * BP + n4 * 4) * 4, src);
    }
    CP_COMMIT();
}

extern "C" __global__ void __launch_bounds__(128) gemm_mma_kernel()
{
    extern __shared__ char smem[];
    uint32_t sb = smem_u32(smem);
    int t = threadIdx.x, wid = t >> 5, lane = t & 31;
    int wr = (wid >> 1) * 64;           // warp row base
    int wc = (wid & 1) * 64;            // warp col base
    int lr = lane >> 2, lc = lane & 3;

    const float* Ag = g_wf + (size_t)blockIdx.x * 128 * KC;

    float acc[4][8][4];
    #pragma unroll
    for (int mi = 0; mi < 4; mi++)
        #pragma unroll
        for (int ni = 0; ni < 8; ni++)
            #pragma unroll
            for (int j = 0; j < 4; j++) acc[mi][ni][j] = 0.0f;

    issue_chunk(sb, sb + A_BYTES, Ag, 0, t);

    for (int c = 0; c < 30; c++) {
        int b = c & 1;
        if (c + 1 < 30)
            issue_chunk(sb + (1 - b) * BUF_BYTES, sb + (1 - b) * BUF_BYTES + A_BYTES, Ag, c + 1, t);
        if (c + 1 < 30) { CP_WAIT(1); } else { CP_WAIT(0); }
        __syncthreads();

        const uint32_t* As = (const uint32_t*)(smem + b * BUF_BYTES);
        const uint32_t* Bs = (const uint32_t*)(smem + b * BUF_BYTES + A_BYTES);

        #pragma unroll
        for (int ks = 0; ks < 4; ks++) {
            int k4 = ks * 8;
            uint32_t a[4][4];
            #pragma unroll
            for (int mi = 0; mi < 4; mi++) {
                int rb = wr + mi * 16;
                a[mi][0] = As[(rb + lr)     * AP + k4 + lc];
                a[mi][1] = As[(rb + lr + 8) * AP + k4 + lc];
                a[mi][2] = As[(rb + lr)     * AP + k4 + lc + 4];
                a[mi][3] = As[(rb + lr + 8) * AP + k4 + lc + 4];
            }
            uint32_t bf[8][2];
            #pragma unroll
            for (int ni = 0; ni < 8; ni++) {
                int cb = wc + ni * 8 + lr;
                bf[ni][0] = Bs[(k4 + lc)     * BP + cb];
                bf[ni][1] = Bs[(k4 + lc + 4) * BP + cb];
            }
            #pragma unroll
            for (int mi = 0; mi < 4; mi++)
                #pragma unroll
                for (int ni = 0; ni < 8; ni++)
                    asm volatile(
                        "mma.sync.aligned.m16n8k8.row.col.f32.tf32.tf32.f32 "
                        "{%0,%1,%2,%3}, {%4,%5,%6,%7}, {%8,%9}, {%0,%1,%2,%3};"
                        : "+f"(acc[mi][ni][0]), "+f"(acc[mi][ni][1]),
                          "+f"(acc[mi][ni][2]), "+f"(acc[mi][ni][3])
                        : "r"(a[mi][0]), "r"(a[mi][1]), "r"(a[mi][2]), "r"(a[mi][3]),
                          "r"(bf[ni][0]), "r"(bf[ni][1]));
        }
        __syncthreads();
    }

    // ---- epilogue: stage D in smem, write g_o, per-CTA BN partials --------
    float* sh = (float*)smem;           // [128][SHP]
    #pragma unroll
    for (int mi = 0; mi < 4; mi++) {
        #pragma unroll
        for (int ni = 0; ni < 8; ni++) {
            int r0 = wr + mi * 16 + lr;
            int cc = wc + ni * 8 + 2 * lc;
            *(float2*)&sh[r0 * SHP + cc]       = make_float2(acc[mi][ni][0], acc[mi][ni][1]);
            *(float2*)&sh[(r0 + 8) * SHP + cc] = make_float2(acc[mi][ni][2], acc[mi][ni][3]);
        }
    }
    __syncthreads();

    float* op = g_o + (size_t)blockIdx.x * 128 * COUT;
    #pragma unroll 8
    for (int it = 0; it < 32; it++) {
        int id = it * 128 + t;
        int row = id >> 5, c4 = id & 31;
        ((float4*)op)[id] = *(const float4*)&sh[row * SHP + c4 * 4];
    }

    {
        float s = 0.0f, q = 0.0f;
        #pragma unroll 8
        for (int r = 0; r < 128; r++) {
            float v = sh[r * SHP + t];
            s += v;
            q = fmaf(v, v, q);
        }
        g_ps[blockIdx.x * COUT + t] = s;
        g_pq[blockIdx.x * COUT + t] = q;
    }
}

// -------------------- 5. BN finalize ---------------------------------------
__global__ void __launch_bounds__(128) bn_final_kernel(const float* __restrict__ gamma,
                                                       const float* __restrict__ beta)
{
    int c = threadIdx.x;
    float s = 0.0f, q = 0.0f;
    for (int b = 0; b < 256; b++) {
        s += g_ps[b * COUT + c];
        q += g_pq[b * COUT + c];
    }
    const float inv = 1.0f / (float)MTOT;
    float mu  = s * inv;
    float var = q * inv - mu * mu;
    float sc  = gamma[c] * rsqrtf(var + 1e-5f);
    g_scale[c] = sc;
    g_bias[c]  = beta[c] - mu * sc;
}

// -------------------- 6. apply BN + LeakyReLU ------------------------------
__global__ void __launch_bounds__(256) bn_apply_kernel(float* __restrict__ out)
{
    int i = blockIdx.x * 256 + threadIdx.x;
    int c = i & 127;
    float v = g_o[i] * g_scale[c] + g_bias[c];
    out[i] = (v >= 0.0f) ? v : 0.2f * v;
}

// -------------------- launch -----------------------------------------------
extern "C" void kernel_launch(void* const* d_in, const int* in_sizes, int n_in,
                              void* d_out, int out_size)
{
    const float* xyz    = (const float*)d_in[0];
    const float* feats  = (const float*)d_in[1];
    const float* kpts   = (const float*)d_in[2];
    const float* weight = (const float*)d_in[3];
    const float* gamma  = (const float*)d_in[4];
    const float* beta   = (const float*)d_in[5];
    float*       out    = (float*)d_out;
    (void)in_sizes; (void)n_in; (void)out_size;

    cudaFuncSetAttribute(gemm_mma_kernel, cudaFuncAttributeMaxDynamicSharedMemorySize, GEMM_SMEM);

    ball_query_kernel<<<256, 128>>>(xyz);
    wf_kernel<<<MTOT / 4, 128>>>(xyz, feats, kpts);
    round_w_kernel<<<480, 256>>>(weight);
    gemm_mma_kernel<<<MTOT / 128, 128, GEMM_SMEM>>>();
    bn_final_kernel<<<1, 128>>>(gamma, beta);
    bn_apply_kernel<<<(MTOT * COUT) / 256, 256>>>(out);
}

// round 4
// speedup vs baseline: 2.1026x; 1.3262x over previous
#include <cuda_runtime.h>
#include <cuda_fp16.h>
#include <cstdint>

// ---------------------------------------------------------------------------
// KPConvSimpleBlock: 4-way ball query -> wf(fp16 out) -> fp16 mma GEMM
//                    (+fused BN partials) -> BN finalize -> BN apply + LeakyReLU
// B=8, N=4096 (M=32768), C_IN=64, C_OUT=128, K=15
// Target is plain sm_103 PTX: mma.sync + cp.async only (no tcgen05).
// ---------------------------------------------------------------------------

#define MTOT  32768
#define NPER  4096
#define CIN   64
#define COUT  128
#define KPN   15
#define KC    960
#define SEGC  34            // per-quarter neighbor cap
#define TOTC  48            // concatenated cap (P(exceed) ~ 0)
#define TH2   (0.082f * 0.082f + 1.0e-4f)

// -------------------- device scratch ---------------------------------------
__device__ __half g_wfh[MTOT * KC];     // fp16 wf features [M, 960]
__device__ __half g_bwT[COUT * KC];     // fp16 W^T          [128, 960]
__device__ float  g_o  [MTOT * COUT];
__device__ int    g_nbr4[MTOT * 4 * SEGC];
__device__ int    g_cnt4[MTOT * 4];
__device__ float  g_ps[512 * COUT];
__device__ float  g_pq[512 * COUT];
__device__ float  g_scale[COUT];
__device__ float  g_bias [COUT];

__device__ __forceinline__ uint32_t smem_u32(const void* p) {
    uint32_t a;
    asm("{ .reg .u64 t; cvta.to.shared.u64 t, %1; cvt.u32.u64 %0, t; }" : "=r"(a) : "l"(p));
    return a;
}
#define CP_ASYNC16(dst, src) \
    asm volatile("cp.async.cg.shared.global [%0], [%1], 16;" :: "r"(dst), "l"(src) : "memory")
#define CP_COMMIT()   asm volatile("cp.async.commit_group;" ::: "memory")
#define CP_WAIT(n)    asm volatile("cp.async.wait_group %0;" :: "n"(n) : "memory")

// -------------------- 1. ball query, 4-way candidate split -----------------
// grid = 8 clouds x 32 chunks x 4 quarters = 1024 blocks, 128 threads.
// Block (b,chunk,q) scans candidate tiles [q*8, q*8+8) for its 128 queries.
__global__ void __launch_bounds__(128) ball_query_kernel(const float* __restrict__ xyz)
{
    int bx    = blockIdx.x;
    int quart = bx & 3;
    int chunk = (bx >> 2) & 31;
    int b     = bx >> 7;
    int t     = threadIdx.x;
    int q     = b * NPER + chunk * 128 + t;

    float qx = xyz[3 * q + 0], qy = xyz[3 * q + 1], qz = xyz[3 * q + 2];
    __shared__ float4 cand[128];
    int cnt = 0;
    int* myNbr = g_nbr4 + (size_t)q * (4 * SEGC) + quart * SEGC;

    for (int tile = quart * 8; tile < quart * 8 + 8; tile++) {
        int j = b * NPER + tile * 128 + t;
        float4 c4 = make_float4(xyz[3 * j], xyz[3 * j + 1], xyz[3 * j + 2], 0.0f);
        __syncthreads();
        cand[t] = c4;
        __syncthreads();
        int jbase = b * NPER + tile * 128;
        #pragma unroll 4
        for (int jj = 0; jj < 128; jj++) {
            float4 c = cand[jj];
            float dx = c.x - qx, dy = c.y - qy, dz = c.z - qz;
            float d2 = dx * dx + dy * dy + dz * dz;
            if (d2 <= TH2 && cnt < SEGC) myNbr[cnt++] = jbase + jj;
        }
    }
    g_cnt4[q * 4 + quart] = cnt;
}

// -------------------- 2. wf stage: one warp per point, fp16 output ---------
__global__ void __launch_bounds__(128) wf_kernel(const float* __restrict__ xyz,
                                                 const float* __restrict__ feats,
                                                 const float* __restrict__ kpts)
{
    __shared__ float ws[4][TOTC][16];
    __shared__ int   nidx[4][TOTC];
    __shared__ float kp_s[48];

    int t = threadIdx.x, warp = t >> 5, lane = t & 31;
    if (t < 45) kp_s[t] = kpts[t];

    int m = blockIdx.x * 4 + warp;
    int c0 = g_cnt4[m * 4 + 0], c1 = g_cnt4[m * 4 + 1];
    int c2 = g_cnt4[m * 4 + 2], c3 = g_cnt4[m * 4 + 3];
    int p1 = c0, p2 = c0 + c1, p3 = c0 + c1 + c2;
    int tot = p3 + c3;
    if (tot > TOTC) tot = TOTC;

    float mx = xyz[3 * m], my = xyz[3 * m + 1], mz = xyz[3 * m + 2];
    __syncthreads();

    // Phase A: concatenate segment lists, compute all 15 kernel weights
    for (int p = lane; p < tot; p += 32) {
        int boff, off;
        if      (p < p1) { boff = 0;        off = p;      }
        else if (p < p2) { boff = SEGC;     off = p - p1; }
        else if (p < p3) { boff = 2 * SEGC; off = p - p2; }
        else             { boff = 3 * SEGC; off = p - p3; }
        int nb = g_nbr4[(size_t)m * (4 * SEGC) + boff + off];
        nidx[warp][p] = nb;
        float rx = xyz[3 * nb] - mx, ry = xyz[3 * nb + 1] - my, rz = xyz[3 * nb + 2] - mz;
        #pragma unroll
        for (int k = 0; k < KPN; k++) {
            float dx = rx - kp_s[3 * k], dy = ry - kp_s[3 * k + 1], dz = rz - kp_s[3 * k + 2];
            float d  = sqrtf(dx * dx + dy * dy + dz * dz);
            ws[warp][p][k] = fmaxf(1.0f - d * 25.0f, 0.0f);
        }
    }
    __syncthreads();

    // Phase B: lane handles channel pair (2*lane, 2*lane+1)
    float acc0[KPN], acc1[KPN];
    #pragma unroll
    for (int k = 0; k < KPN; k++) { acc0[k] = 0.0f; acc1[k] = 0.0f; }

    for (int p = 0; p < tot; p++) {
        int nb = nidx[warp][p];
        float2 f = *(const float2*)(feats + (size_t)nb * CIN + 2 * lane);
        const float4* wv = (const float4*)ws[warp][p];
        float4 w0 = wv[0], w1 = wv[1], w2 = wv[2], w3 = wv[3];
        acc0[0]  += w0.x * f.x;  acc1[0]  += w0.x * f.y;
        acc0[1]  += w0.y * f.x;  acc1[1]  += w0.y * f.y;
        acc0[2]  += w0.z * f.x;  acc1[2]  += w0.z * f.y;
        acc0[3]  += w0.w * f.x;  acc1[3]  += w0.w * f.y;
        acc0[4]  += w1.x * f.x;  acc1[4]  += w1.x * f.y;
        acc0[5]  += w1.y * f.x;  acc1[5]  += w1.y * f.y;
        acc0[6]  += w1.z * f.x;  acc1[6]  += w1.z * f.y;
        acc0[7]  += w1.w * f.x;  acc1[7]  += w1.w * f.y;
        acc0[8]  += w2.x * f.x;  acc1[8]  += w2.x * f.y;
        acc0[9]  += w2.y * f.x;  acc1[9]  += w2.y * f.y;
        acc0[10] += w2.z * f.x;  acc1[10] += w2.z * f.y;
        acc0[11] += w2.w * f.x;  acc1[11] += w2.w * f.y;
        acc0[12] += w3.x * f.x;  acc1[12] += w3.x * f.y;
        acc0[13] += w3.y * f.x;  acc1[13] += w3.y * f.y;
        acc0[14] += w3.z * f.x;  acc1[14] += w3.z * f.y;
    }

    __half2* dst = (__half2*)(g_wfh + (size_t)m * KC);
    #pragma unroll
    for (int k = 0; k < KPN; k++)
        dst[k * 32 + lane] = __floats2half2_rn(acc0[k], acc1[k]);
}

// -------------------- 3. W -> W^T fp16 [128][960] --------------------------
__global__ void __launch_bounds__(256) wt_kernel(const float* __restrict__ W)
{
    int i = blockIdx.x * 256 + threadIdx.x;   // 480 blocks, write-coalesced
    int n = i / KC, k = i - n * KC;
    g_bwT[i] = __float2half_rn(W[k * COUT + n]);
}

// -------------------- 4. fp16 mma GEMM + fused BN partials -----------------
// CTA: 128x128 tile, 256 threads (8 warps, each 32x64), K-chunks of 32,
// cp.async double buffer. smem pitch 40 halfs (80 B) -> conflict-free frags.
#define PH       40
#define TILE_B   (128 * PH * 2)          // 10240 B per operand tile
#define BUF_B    (2 * TILE_B)            // A + B per stage
#define SHP      132
#define GEMM_SMEM (128 * SHP * 4)        // 67584 >= 2*BUF_B = 40960

__device__ __forceinline__ void issue_chunk(uint32_t buf, const __half* __restrict__ Ag,
                                            int c, int t)
{
    #pragma unroll
    for (int i = 0; i < 2; i++) {        // A: 512 x 16B
        int id = i * 256 + t;
        int row = id >> 2, s16 = id & 3;
        CP_ASYNC16(buf + row * (PH * 2) + s16 * 16,
                   Ag + (size_t)row * KC + c * 32 + s16 * 8);
    }
    #pragma unroll
    for (int i = 0; i < 2; i++) {        // B: 512 x 16B
        int id = i * 256 + t;
        int row = id >> 2, s16 = id & 3;
        CP_ASYNC16(buf + TILE_B + row * (PH * 2) + s16 * 16,
                   g_bwT + (size_t)row * KC + c * 32 + s16 * 8);
    }
    CP_COMMIT();
}

extern "C" __global__ void __launch_bounds__(256) gemm_mma_kernel()
{
    extern __shared__ char smem[];
    uint32_t sb = smem_u32(smem);
    int t = threadIdx.x, wid = t >> 5, lane = t & 31;
    int wr = (wid >> 1) * 32;            // warp row base (4 groups)
    int wc = (wid & 1) * 64;             // warp col base (2 groups)
    int lr = lane >> 2, lc = lane & 3;

    const __half* Ag = g_wfh + (size_t)blockIdx.x * 128 * KC;

    float acc[2][8][4];
    #pragma unroll
    for (int mi = 0; mi < 2; mi++)
        #pragma unroll
        for (int ni = 0; ni < 8; ni++)
            #pragma unroll
            for (int j = 0; j < 4; j++) acc[mi][ni][j] = 0.0f;

    issue_chunk(sb, Ag, 0, t);

    for (int c = 0; c < 30; c++) {
        int b = c & 1;
        if (c + 1 < 30) issue_chunk(sb + (1 - b) * BUF_B, Ag, c + 1, t);
        if (c + 1 < 30) { CP_WAIT(1); } else { CP_WAIT(0); }
        __syncthreads();

        const char* As = smem + b * BUF_B;
        const char* Bs = smem + b * BUF_B + TILE_B;

        #pragma unroll
        for (int ks = 0; ks < 2; ks++) {
            int kb = ks * 16;
            uint32_t a[2][4];
            #pragma unroll
            for (int mi = 0; mi < 2; mi++) {
                int r0 = wr + mi * 16 + lr;
                a[mi][0] = *(const uint32_t*)(As + r0 * (PH * 2)       + (kb + 2 * lc) * 2);
                a[mi][1] = *(const uint32_t*)(As + (r0 + 8) * (PH * 2) + (kb + 2 * lc) * 2);
                a[mi][2] = *(const uint32_t*)(As + r0 * (PH * 2)       + (kb + 8 + 2 * lc) * 2);
                a[mi][3] = *(const uint32_t*)(As + (r0 + 8) * (PH * 2) + (kb + 8 + 2 * lc) * 2);
            }
            uint32_t bf[8][2];
            #pragma unroll
            for (int ni = 0; ni < 8; ni++) {
                int n0 = wc + ni * 8 + lr;
                bf[ni][0] = *(const uint32_t*)(Bs + n0 * (PH * 2) + (kb + 2 * lc) * 2);
                bf[ni][1] = *(const uint32_t*)(Bs + n0 * (PH * 2) + (kb + 8 + 2 * lc) * 2);
            }
            #pragma unroll
            for (int mi = 0; mi < 2; mi++)
                #pragma unroll
                for (int ni = 0; ni < 8; ni++)
                    asm volatile(
                        "mma.sync.aligned.m16n8k16.row.col.f32.f16.f16.f32 "
                        "{%0,%1,%2,%3}, {%4,%5,%6,%7}, {%8,%9}, {%0,%1,%2,%3};"
                        : "+f"(acc[mi][ni][0]), "+f"(acc[mi][ni][1]),
                          "+f"(acc[mi][ni][2]), "+f"(acc[mi][ni][3])
                        : "r"(a[mi][0]), "r"(a[mi][1]), "r"(a[mi][2]), "r"(a[mi][3]),
                          "r"(bf[ni][0]), "r"(bf[ni][1]));
        }
        __syncthreads();
    }

    // ---- epilogue: stage D, write g_o, per-CTA BN partials ----------------
    float* sh = (float*)smem;            // [128][SHP]
    #pragma unroll
    for (int mi = 0; mi < 2; mi++) {
        #pragma unroll
        for (int ni = 0; ni < 8; ni++) {
            int r0 = wr + mi * 16 + lr;
            int cc = wc + ni * 8 + 2 * lc;
            *(float2*)&sh[r0 * SHP + cc]       = make_float2(acc[mi][ni][0], acc[mi][ni][1]);
            *(float2*)&sh[(r0 + 8) * SHP + cc] = make_float2(acc[mi][ni][2], acc[mi][ni][3]);
        }
    }
    __syncthreads();

    float* op = g_o + (size_t)blockIdx.x * 128 * COUT;
    #pragma unroll
    for (int it = 0; it < 16; it++) {
        int id = it * 256 + t;
        int row = id >> 5, c4 = id & 31;
        ((float4*)op)[id] = *(const float4*)&sh[row * SHP + c4 * 4];
    }

    {
        int c    = t & 127;
        int half = t >> 7;
        float s = 0.0f, q = 0.0f;
        #pragma unroll 8
        for (int r = half * 64; r < half * 64 + 64; r++) {
            float v = sh[r * SHP + c];
            s += v;
            q = fmaf(v, v, q);
        }
        g_ps[(blockIdx.x * 2 + half) * COUT + c] = s;
        g_pq[(blockIdx.x * 2 + half) * COUT + c] = q;
    }
}

// -------------------- 5. BN finalize ---------------------------------------
__global__ void __launch_bounds__(128) bn_final_kernel(const float* __restrict__ gamma,
                                                       const float* __restrict__ beta)
{
    int c = threadIdx.x;
    float s = 0.0f, q = 0.0f;
    for (int b = 0; b < 512; b++) {
        s += g_ps[b * COUT + c];
        q += g_pq[b * COUT + c];
    }
    const float inv = 1.0f / (float)MTOT;
    float mu  = s * inv;
    float var = q * inv - mu * mu;
    float sc  = gamma[c] * rsqrtf(var + 1e-5f);
    g_scale[c] = sc;
    g_bias[c]  = beta[c] - mu * sc;
}

// -------------------- 6. apply BN + LeakyReLU (vectorized) -----------------
__global__ void __launch_bounds__(256) bn_apply_kernel(float* __restrict__ out)
{
    int i4 = blockIdx.x * 256 + threadIdx.x;      // over MTOT*COUT/4
    int cb = (i4 & 31) * 4;                       // column base within 128
    float4 v = ((const float4*)g_o)[i4];
    float4 sc = *(const float4*)&g_scale[cb];
    float4 bs = *(const float4*)&g_bias[cb];
    float4 r;
    r.x = v.x * sc.x + bs.x;  r.x = (r.x >= 0.0f) ? r.x : 0.2f * r.x;
    r.y = v.y * sc.y + bs.y;  r.y = (r.y >= 0.0f) ? r.y : 0.2f * r.y;
    r.z = v.z * sc.z + bs.z;  r.z = (r.z >= 0.0f) ? r.z : 0.2f * r.z;
    r.w = v.w * sc.w + bs.w;  r.w = (r.w >= 0.0f) ? r.w : 0.2f * r.w;
    ((float4*)out)[i4] = r;
}

// -------------------- launch -----------------------------------------------
extern "C" void kernel_launch(void* const* d_in, const int* in_sizes, int n_in,
                              void* d_out, int out_size)
{
    const float* xyz    = (const float*)d_in[0];
    const float* feats  = (const float*)d_in[1];
    const float* kpts   = (const float*)d_in[2];
    const float* weight = (const float*)d_in[3];
    const float* gamma  = (const float*)d_in[4];
    const float* beta   = (const float*)d_in[5];
    float*       out    = (float*)d_out;
    (void)in_sizes; (void)n_in; (void)out_size;

    cudaFuncSetAttribute(gemm_mma_kernel, cudaFuncAttributeMaxDynamicSharedMemorySize, GEMM_SMEM);

    ball_query_kernel<<<1024, 128>>>(xyz);
    wf_kernel<<<MTOT / 4, 128>>>(xyz, feats, kpts);
    wt_kernel<<<480, 256>>>(weight);
    gemm_mma_kernel<<<MTOT / 128, 256, GEMM_SMEM>>>();
    bn_final_kernel<<<1, 128>>>(gamma, beta);
    bn_apply_kernel<<<(MTOT * COUT) / 1024, 256>>>(out);
}

// round 5
// speedup vs baseline: 2.4812x; 1.1801x over previous
#include <cuda_runtime.h>
#include <cuda_fp16.h>
#include <cstdint>

// ---------------------------------------------------------------------------
// KPConvSimpleBlock: spatial-grid neighbor search fused with wf (fp16 out)
//   -> fp16 mma GEMM (+fused BN partials, 2 CTA/SM) -> BN finalize -> apply.
// B=8, N=4096 (M=32768), C_IN=64, C_OUT=128, K=15. Plain sm_103 PTX only.
// ---------------------------------------------------------------------------

#define MTOT  32768
#define NPER  4096
#define CIN   64
#define COUT  128
#define KPN   15
#define KC    960
#define TOTC  48                 // neighbor cap per point (avg ~13)
#define TH2   (0.082f * 0.082f + 1.0e-4f)

#define GD    10                 // grid cells per dim (cell 0.1 >= reach 0.0826)
#define NCELL 1000
#define CAP   28                 // bucket capacity (Poisson lam~4.1, overflow ~0)
#define CANDC 512                // per-warp candidate buffer

// -------------------- device scratch ---------------------------------------
__device__ __half g_wfh[MTOT * KC];
__device__ __half g_bwT[COUT * KC];
__device__ float  g_o  [MTOT * COUT];
__device__ int    g_ccnt[8 * NCELL];
__device__ int    g_cpts[8 * NCELL * CAP];
__device__ float  g_ps[1024 * COUT];
__device__ float  g_pq[1024 * COUT];
__device__ float  g_scale[COUT];
__device__ float  g_bias [COUT];

__device__ __forceinline__ uint32_t smem_u32(const void* p) {
    uint32_t a;
    asm("{ .reg .u64 t; cvta.to.shared.u64 t, %1; cvt.u32.u64 %0, t; }" : "=r"(a) : "l"(p));
    return a;
}
#define CP_ASYNC16(dst, src) \
    asm volatile("cp.async.cg.shared.global [%0], [%1], 16;" :: "r"(dst), "l"(src) : "memory")
#define CP_COMMIT()   asm volatile("cp.async.commit_group;" ::: "memory")
#define CP_WAIT(n)    asm volatile("cp.async.wait_group %0;" :: "n"(n) : "memory")

__device__ __forceinline__ int cell_of(float x, float y, float z) {
    int cx = min((int)(x * (float)GD), GD - 1);
    int cy = min((int)(y * (float)GD), GD - 1);
    int cz = min((int)(z * (float)GD), GD - 1);
    return (cx * GD + cy) * GD + cz;
}

// -------------------- 1a. zero cell counts ---------------------------------
__global__ void __launch_bounds__(1024) zero_cnt_kernel()
{
    int i = blockIdx.x * 1024 + threadIdx.x;
    if (i < 8 * NCELL) g_ccnt[i] = 0;
}

// -------------------- 1b. scatter points into buckets ----------------------
__global__ void __launch_bounds__(1024) scatter_kernel(const float* __restrict__ xyz)
{
    int i = blockIdx.x * 1024 + threadIdx.x;     // 32 blocks
    int b = i >> 12;
    int cell = b * NCELL + cell_of(xyz[3 * i], xyz[3 * i + 1], xyz[3 * i + 2]);
    int slot = atomicAdd(&g_ccnt[cell], 1);
    if (slot < CAP) g_cpts[cell * CAP + slot] = i;
}

// -------------------- 1c. sort each bucket ascending (determinism) ---------
__global__ void __launch_bounds__(256) sortb_kernel()
{
    int cell = blockIdx.x * 256 + threadIdx.x;   // 32 blocks >= 8000 cells
    if (cell >= 8 * NCELL) return;
    int cnt = min(g_ccnt[cell], CAP);
    int* p = g_cpts + cell * CAP;
    for (int i = 1; i < cnt; i++) {
        int v = p[i], j = i - 1;
        while (j >= 0 && p[j] > v) { p[j + 1] = p[j]; j--; }
        p[j + 1] = v;
    }
}

// -------------------- 2. fused neighbor search + wf (fp16 out) -------------
// warp per point; 4 points per 128-thread block.
__global__ void __launch_bounds__(128) wf_fused_kernel(const float* __restrict__ xyz,
                                                       const float* __restrict__ feats,
                                                       const float* __restrict__ kpts)
{
    __shared__ int   cand[4][CANDC];
    __shared__ int   nbr [4][TOTC];
    __shared__ float ws  [4][TOTC][16];
    __shared__ float kp_s[48];

    int t = threadIdx.x, warp = t >> 5, lane = t & 31;
    if (t < 45) kp_s[t] = kpts[t];
    __syncthreads();

    int m = blockIdx.x * 4 + warp;
    int b = m >> 12;
    float qx = xyz[3 * m], qy = xyz[3 * m + 1], qz = xyz[3 * m + 2];

    int cx = min((int)(qx * (float)GD), GD - 1);
    int cy = min((int)(qy * (float)GD), GD - 1);
    int cz = min((int)(qz * (float)GD), GD - 1);

    // ---- gather stencil candidates (deterministic order) ------------------
    int cnt = 0, cellid = -1;
    if (lane < 27) {
        int dx = lane / 9 - 1, dy = (lane / 3) % 3 - 1, dz = lane % 3 - 1;
        int x2 = cx + dx, y2 = cy + dy, z2 = cz + dz;
        if (x2 >= 0 && x2 < GD && y2 >= 0 && y2 < GD && z2 >= 0 && z2 < GD) {
            cellid = b * NCELL + (x2 * GD + y2) * GD + z2;
            cnt = min(g_ccnt[cellid], CAP);
        }
    }
    int off = cnt;
    #pragma unroll
    for (int s = 1; s < 32; s <<= 1) {
        int v = __shfl_up_sync(0xffffffffu, off, s);
        if (lane >= s) off += v;
    }
    int T = __shfl_sync(0xffffffffu, off, 31);
    off -= cnt;
    for (int i = 0; i < cnt; i++) cand[warp][off + i] = g_cpts[cellid * CAP + i];
    __syncwarp();

    // ---- test candidates, compact neighbors, compute weights inline -------
    int nbcnt = 0;
    for (int base = 0; base < T; base += 32) {
        int p = base + lane;
        bool keep = false;
        int nb = 0;
        float rx = 0.0f, ry = 0.0f, rz = 0.0f;
        if (p < T) {
            nb = cand[warp][p];
            rx = xyz[3 * nb] - qx;
            ry = xyz[3 * nb + 1] - qy;
            rz = xyz[3 * nb + 2] - qz;
            keep = (rx * rx + ry * ry + rz * rz) <= TH2;
        }
        unsigned mask = __ballot_sync(0xffffffffu, keep);
        int idx = nbcnt + __popc(mask & ((1u << lane) - 1u));
        if (keep && idx < TOTC) {
            nbr[warp][idx] = nb;
            #pragma unroll
            for (int k = 0; k < KPN; k++) {
                float ddx = rx - kp_s[3 * k];
                float ddy = ry - kp_s[3 * k + 1];
                float ddz = rz - kp_s[3 * k + 2];
                float d = sqrtf(ddx * ddx + ddy * ddy + ddz * ddz);
                ws[warp][idx][k] = fmaxf(1.0f - d * 25.0f, 0.0f);
            }
        }
        nbcnt += __popc(mask);
    }
    if (nbcnt > TOTC) nbcnt = TOTC;
    __syncwarp();

    // ---- phase B: lane accumulates channel pair (2*lane, 2*lane+1) --------
    float acc0[KPN], acc1[KPN];
    #pragma unroll
    for (int k = 0; k < KPN; k++) { acc0[k] = 0.0f; acc1[k] = 0.0f; }

    for (int p = 0; p < nbcnt; p++) {
        int nb = nbr[warp][p];
        float2 f = *(const float2*)(feats + (size_t)nb * CIN + 2 * lane);
        const float4* wv = (const float4*)ws[warp][p];
        float4 w0 = wv[0], w1 = wv[1], w2 = wv[2], w3 = wv[3];
        acc0[0]  += w0.x * f.x;  acc1[0]  += w0.x * f.y;
        acc0[1]  += w0.y * f.x;  acc1[1]  += w0.y * f.y;
        acc0[2]  += w0.z * f.x;  acc1[2]  += w0.z * f.y;
        acc0[3]  += w0.w * f.x;  acc1[3]  += w0.w * f.y;
        acc0[4]  += w1.x * f.x;  acc1[4]  += w1.x * f.y;
        acc0[5]  += w1.y * f.x;  acc1[5]  += w1.y * f.y;
        acc0[6]  += w1.z * f.x;  acc1[6]  += w1.z * f.y;
        acc0[7]  += w1.w * f.x;  acc1[7]  += w1.w * f.y;
        acc0[8]  += w2.x * f.x;  acc1[8]  += w2.x * f.y;
        acc0[9]  += w2.y * f.x;  acc1[9]  += w2.y * f.y;
        acc0[10] += w2.z * f.x;  acc1[10] += w2.z * f.y;
        acc0[11] += w2.w * f.x;  acc1[11] += w2.w * f.y;
        acc0[12] += w3.x * f.x;  acc1[12] += w3.x * f.y;
        acc0[13] += w3.y * f.x;  acc1[13] += w3.y * f.y;
        acc0[14] += w3.z * f.x;  acc1[14] += w3.z * f.y;
    }

    __half2* dst = (__half2*)(g_wfh + (size_t)m * KC);
    #pragma unroll
    for (int k = 0; k < KPN; k++)
        dst[k * 32 + lane] = __floats2half2_rn(acc0[k], acc1[k]);
}

// -------------------- 3. W -> W^T fp16 [128][960] --------------------------
__global__ void __launch_bounds__(256) wt_kernel(const float* __restrict__ W)
{
    int i = blockIdx.x * 256 + threadIdx.x;
    int n = i / KC, k = i - n * KC;
    g_bwT[i] = __float2half_rn(W[k * COUT + n]);
}

// -------------------- 4. fp16 mma GEMM + fused BN partials -----------------
#define PH       40
#define TILE_B   (128 * PH * 2)
#define BUF_B    (2 * TILE_B)
#define SHP      132
#define GEMM_SMEM (2 * BUF_B)            // 40960 >= 64*SHP*4 = 33792 staging

__device__ __forceinline__ void issue_chunk(uint32_t buf, const __half* __restrict__ Ag,
                                            int c, int t)
{
    #pragma unroll
    for (int i = 0; i < 2; i++) {
        int id = i * 256 + t;
        int row = id >> 2, s16 = id & 3;
        CP_ASYNC16(buf + row * (PH * 2) + s16 * 16,
                   Ag + (size_t)row * KC + c * 32 + s16 * 8);
    }
    #pragma unroll
    for (int i = 0; i < 2; i++) {
        int id = i * 256 + t;
        int row = id >> 2, s16 = id & 3;
        CP_ASYNC16(buf + TILE_B + row * (PH * 2) + s16 * 16,
                   g_bwT + (size_t)row * KC + c * 32 + s16 * 8);
    }
    CP_COMMIT();
}

extern "C" __global__ void __launch_bounds__(256, 2) gemm_mma_kernel()
{
    extern __shared__ char smem[];
    int t = threadIdx.x, wid = t >> 5, lane = t & 31;
    int wr = (wid >> 1) * 32;
    int wc = (wid & 1) * 64;
    int lr = lane >> 2, lc = lane & 3;

    const __half* Ag = g_wfh + (size_t)blockIdx.x * 128 * KC;

    float acc[2][8][4];
    #pragma unroll
    for (int mi = 0; mi < 2; mi++)
        #pragma unroll
        for (int ni = 0; ni < 8; ni++)
            #pragma unroll
            for (int j = 0; j < 4; j++) acc[mi][ni][j] = 0.0f;

    issue_chunk(smem_u32(smem), Ag, 0, t);
    uint32_t sb = smem_u32(smem);

    for (int c = 0; c < 30; c++) {
        int b = c & 1;
        if (c + 1 < 30) issue_chunk(sb + (1 - b) * BUF_B, Ag, c + 1, t);
        if (c + 1 < 30) { CP_WAIT(1); } else { CP_WAIT(0); }
        __syncthreads();

        const char* As = smem + b * BUF_B;
        const char* Bs = smem + b * BUF_B + TILE_B;

        #pragma unroll
        for (int ks = 0; ks < 2; ks++) {
            int kb = ks * 16;
            uint32_t a[2][4];
            #pragma unroll
            for (int mi = 0; mi < 2; mi++) {
                int r0 = wr + mi * 16 + lr;
                a[mi][0] = *(const uint32_t*)(As + r0 * (PH * 2)       + (kb + 2 * lc) * 2);
                a[mi][1] = *(const uint32_t*)(As + (r0 + 8) * (PH * 2) + (kb + 2 * lc) * 2);
                a[mi][2] = *(const uint32_t*)(As + r0 * (PH * 2)       + (kb + 8 + 2 * lc) * 2);
                a[mi][3] = *(const uint32_t*)(As + (r0 + 8) * (PH * 2) + (kb + 8 + 2 * lc) * 2);
            }
            uint32_t bf[8][2];
            #pragma unroll
            for (int ni = 0; ni < 8; ni++) {
                int n0 = wc + ni * 8 + lr;
                bf[ni][0] = *(const uint32_t*)(Bs + n0 * (PH * 2) + (kb + 2 * lc) * 2);
                bf[ni][1] = *(const uint32_t*)(Bs + n0 * (PH * 2) + (kb + 8 + 2 * lc) * 2);
            }
            #pragma unroll
            for (int mi = 0; mi < 2; mi++)
                #pragma unroll
                for (int ni = 0; ni < 8; ni++)
                    asm volatile(
                        "mma.sync.aligned.m16n8k16.row.col.f32.f16.f16.f32 "
                        "{%0,%1,%2,%3}, {%4,%5,%6,%7}, {%8,%9}, {%0,%1,%2,%3};"
                        : "+f"(acc[mi][ni][0]), "+f"(acc[mi][ni][1]),
                          "+f"(acc[mi][ni][2]), "+f"(acc[mi][ni][3])
                        : "r"(a[mi][0]), "r"(a[mi][1]), "r"(a[mi][2]), "r"(a[mi][3]),
                          "r"(bf[ni][0]), "r"(bf[ni][1]));
        }
        __syncthreads();
    }

    // ---- two-pass epilogue (64 rows/pass): g_o + BN partials --------------
    float* sh = (float*)smem;            // [64][SHP]
    #pragma unroll
    for (int h = 0; h < 2; h++) {
        __syncthreads();
        if ((wid >> 2) == h) {
            #pragma unroll
            for (int mi = 0; mi < 2; mi++) {
                #pragma unroll
                for (int ni = 0; ni < 8; ni++) {
                    int r0 = wr + mi * 16 + lr - h * 64;
                    int cc = wc + ni * 8 + 2 * lc;
                    *(float2*)&sh[r0 * SHP + cc]       = make_float2(acc[mi][ni][0], acc[mi][ni][1]);
                    *(float2*)&sh[(r0 + 8) * SHP + cc] = make_float2(acc[mi][ni][2], acc[mi][ni][3]);
                }
            }
        }
        __syncthreads();

        float* op = g_o + ((size_t)blockIdx.x * 128 + h * 64) * COUT;
        #pragma unroll
        for (int it = 0; it < 8; it++) {
            int id = it * 256 + t;
            int row = id >> 5, c4 = id & 31;
            ((float4*)op)[id] = *(const float4*)&sh[row * SHP + c4 * 4];
        }

        int cch = t & 127, sub = t >> 7;
        float s = 0.0f, q = 0.0f;
        #pragma unroll 8
        for (int r = sub * 32; r < sub * 32 + 32; r++) {
            float v = sh[r * SHP + cch];
            s += v;
            q = fmaf(v, v, q);
        }
        g_ps[((size_t)blockIdx.x * 4 + h * 2 + sub) * COUT + cch] = s;
        g_pq[((size_t)blockIdx.x * 4 + h * 2 + sub) * COUT + cch] = q;
    }
}

// -------------------- 5. BN finalize ---------------------------------------
__global__ void __launch_bounds__(128) bn_final_kernel(const float* __restrict__ gamma,
                                                       const float* __restrict__ beta)
{
    int c = threadIdx.x;
    float s = 0.0f, q = 0.0f;
    #pragma unroll 8
    for (int b = 0; b < 1024; b++) {
        s += g_ps[b * COUT + c];
        q += g_pq[b * COUT + c];
    }
    const float inv = 1.0f / (float)MTOT;
    float mu  = s * inv;
    float var = q * inv - mu * mu;
    float sc  = gamma[c] * rsqrtf(var + 1e-5f);
    g_scale[c] = sc;
    g_bias[c]  = beta[c] - mu * sc;
}

// -------------------- 6. apply BN + LeakyReLU ------------------------------
__global__ void __launch_bounds__(256) bn_apply_kernel(float* __restrict__ out)
{
    int i4 = blockIdx.x * 256 + threadIdx.x;
    int cb = (i4 & 31) * 4;
    float4 v = ((const float4*)g_o)[i4];
    float4 sc = *(const float4*)&g_scale[cb];
    float4 bs = *(const float4*)&g_bias[cb];
    float4 r;
    r.x = v.x * sc.x + bs.x;  r.x = (r.x >= 0.0f) ? r.x : 0.2f * r.x;
    r.y = v.y * sc.y + bs.y;  r.y = (r.y >= 0.0f) ? r.y : 0.2f * r.y;
    r.z = v.z * sc.z + bs.z;  r.z = (r.z >= 0.0f) ? r.z : 0.2f * r.z;
    r.w = v.w * sc.w + bs.w;  r.w = (r.w >= 0.0f) ? r.w : 0.2f * r.w;
    ((float4*)out)[i4] = r;
}

// -------------------- launch -----------------------------------------------
extern "C" void kernel_launch(void* const* d_in, const int* in_sizes, int n_in,
                              void* d_out, int out_size)
{
    const float* xyz    = (const float*)d_in[0];
    const float* feats  = (const float*)d_in[1];
    const float* kpts   = (const float*)d_in[2];
    const float* weight = (const float*)d_in[3];
    const float* gamma  = (const float*)d_in[4];
    const float* beta   = (const float*)d_in[5];
    float*       out    = (float*)d_out;
    (void)in_sizes; (void)n_in; (void)out_size;

    cudaFuncSetAttribute(gemm_mma_kernel, cudaFuncAttributeMaxDynamicSharedMemorySize, GEMM_SMEM);

    zero_cnt_kernel<<<8, 1024>>>();
    scatter_kernel<<<32, 1024>>>(xyz);
    sortb_kernel<<<32, 256>>>();
    wf_fused_kernel<<<MTOT / 4, 128>>>(xyz, feats, kpts);
    wt_kernel<<<480, 256>>>(weight);
    gemm_mma_kernel<<<MTOT / 128, 256, GEMM_SMEM>>>();
    bn_final_kernel<<<1, 128>>>(gamma, beta);
    bn_apply_kernel<<<(MTOT * COUT) / 1024, 256>>>(out);
}

// round 6
// speedup vs baseline: 2.7425x; 1.1053x over previous
#include <cuda_runtime.h>
#include <cuda_fp16.h>
#include <cstdint>

// ---------------------------------------------------------------------------
// KPConvSimpleBlock: grid neighbor search + wf via per-point mma (fp16)
//   -> fp16 mma GEMM (+fused BN partials) -> 2-stage BN -> apply + LeakyReLU
// B=8, N=4096 (M=32768), C_IN=64, C_OUT=128, K=15. Plain sm_103 PTX only.
// ---------------------------------------------------------------------------

#define MTOT  32768
#define NPER  4096
#define CIN   64
#define COUT  128
#define KPN   15
#define KC    960
#define TOTC  48
#define TH2   (0.082f * 0.082f + 1.0e-4f)

#define GD    10
#define NCELL 1000
#define CAP   28
#define CANDC 512

#define WSP   50                 // wsT pitch (halfs): banks 25r+c all distinct
#define FSP   26                 // fsT pitch (halfs): 13 coprime 32

// -------------------- device scratch ---------------------------------------
__device__ __half g_wfh[MTOT * KC];
__device__ __half g_bwT[COUT * KC];
__device__ float  g_o  [MTOT * COUT];
__device__ int    g_ccnt[8 * NCELL];
__device__ int    g_cpts[8 * NCELL * CAP];
__device__ float  g_ps[1024 * COUT];
__device__ float  g_pq[1024 * COUT];
__device__ float  g_ps2[32 * COUT];
__device__ float  g_pq2[32 * COUT];
__device__ float  g_scale[COUT];
__device__ float  g_bias [COUT];

__device__ __forceinline__ uint32_t smem_u32(const void* p) {
    uint32_t a;
    asm("{ .reg .u64 t; cvta.to.shared.u64 t, %1; cvt.u32.u64 %0, t; }" : "=r"(a) : "l"(p));
    return a;
}
#define CP_ASYNC16(dst, src) \
    asm volatile("cp.async.cg.shared.global [%0], [%1], 16;" :: "r"(dst), "l"(src) : "memory")
#define CP_COMMIT()   asm volatile("cp.async.commit_group;" ::: "memory")
#define CP_WAIT(n)    asm volatile("cp.async.wait_group %0;" :: "n"(n) : "memory")

__device__ __forceinline__ int cell_of(float x, float y, float z) {
    int cx = min((int)(x * (float)GD), GD - 1);
    int cy = min((int)(y * (float)GD), GD - 1);
    int cz = min((int)(z * (float)GD), GD - 1);
    return (cx * GD + cy) * GD + cz;
}

// -------------------- 1. grid build ----------------------------------------
__global__ void __launch_bounds__(1024) zero_cnt_kernel()
{
    int i = blockIdx.x * 1024 + threadIdx.x;
    if (i < 8 * NCELL) g_ccnt[i] = 0;
}

__global__ void __launch_bounds__(1024) scatter_kernel(const float* __restrict__ xyz)
{
    int i = blockIdx.x * 1024 + threadIdx.x;
    int b = i >> 12;
    int cell = b * NCELL + cell_of(xyz[3 * i], xyz[3 * i + 1], xyz[3 * i + 2]);
    int slot = atomicAdd(&g_ccnt[cell], 1);
    if (slot < CAP) g_cpts[cell * CAP + slot] = i;
}

__global__ void __launch_bounds__(256) sortb_kernel()
{
    int cell = blockIdx.x * 256 + threadIdx.x;
    if (cell >= 8 * NCELL) return;
    int cnt = min(g_ccnt[cell], CAP);
    int* p = g_cpts + cell * CAP;
    for (int i = 1; i < cnt; i++) {
        int v = p[i], j = i - 1;
        while (j >= 0 && p[j] > v) { p[j + 1] = p[j]; j--; }
        p[j + 1] = v;
    }
}

// -------------------- 2. fused search + wf via tensor mma ------------------
// warp per point. wf[16,64] = w[16,K] @ f[K,64] with K-tiles of 16 neighbors.
__global__ void __launch_bounds__(128) wf_fused_kernel(const float* __restrict__ xyz,
                                                       const float* __restrict__ feats,
                                                       const float* __restrict__ kpts)
{
    __shared__ int    cand[4][CANDC];
    __shared__ int    nbr [4][TOTC];
    __shared__ __align__(16) __half wsT[4][16][WSP];   // [kp][nbr]
    __shared__ __align__(16) __half fsT[4][64][FSP];   // [ch][nbr-in-tile]
    __shared__ float  kp_s[48];

    int t = threadIdx.x, warp = t >> 5, lane = t & 31;
    if (t < 45) kp_s[t] = kpts[t];
    __syncthreads();

    int m = blockIdx.x * 4 + warp;
    int b = m >> 12;
    float qx = xyz[3 * m], qy = xyz[3 * m + 1], qz = xyz[3 * m + 2];

    // zero wsT (covers kp pad row 15 and neighbor padding)
    {
        uint32_t* wz = (uint32_t*)&wsT[warp][0][0];    // 16*50/2 = 400 words
        for (int i = lane; i < 400; i += 32) wz[i] = 0u;
    }

    int cx = min((int)(qx * (float)GD), GD - 1);
    int cy = min((int)(qy * (float)GD), GD - 1);
    int cz = min((int)(qz * (float)GD), GD - 1);

    // ---- gather stencil candidates ----------------------------------------
    int cnt = 0, cellid = -1;
    if (lane < 27) {
        int dx = lane / 9 - 1, dy = (lane / 3) % 3 - 1, dz = lane % 3 - 1;
        int x2 = cx + dx, y2 = cy + dy, z2 = cz + dz;
        if (x2 >= 0 && x2 < GD && y2 >= 0 && y2 < GD && z2 >= 0 && z2 < GD) {
            cellid = b * NCELL + (x2 * GD + y2) * GD + z2;
            cnt = min(g_ccnt[cellid], CAP);
        }
    }
    int off = cnt;
    #pragma unroll
    for (int s = 1; s < 32; s <<= 1) {
        int v = __shfl_up_sync(0xffffffffu, off, s);
        if (lane >= s) off += v;
    }
    int T = __shfl_sync(0xffffffffu, off, 31);
    off -= cnt;
    for (int i = 0; i < cnt; i++) cand[warp][off + i] = g_cpts[cellid * CAP + i];
    __syncwarp();

    // ---- test candidates, compact, write fp16 weights wsT[k][idx] ---------
    int nbcnt = 0;
    for (int base = 0; base < T; base += 32) {
        int p = base + lane;
        bool keep = false;
        int nb = 0;
        float rx = 0.0f, ry = 0.0f, rz = 0.0f;
        if (p < T) {
            nb = cand[warp][p];
            rx = xyz[3 * nb] - qx;
            ry = xyz[3 * nb + 1] - qy;
            rz = xyz[3 * nb + 2] - qz;
            keep = (rx * rx + ry * ry + rz * rz) <= TH2;
        }
        unsigned mask = __ballot_sync(0xffffffffu, keep);
        int idx = nbcnt + __popc(mask & ((1u << lane) - 1u));
        if (keep && idx < TOTC) {
            nbr[warp][idx] = nb;
            #pragma unroll
            for (int k = 0; k < KPN; k++) {
                float ddx = rx - kp_s[3 * k];
                float ddy = ry - kp_s[3 * k + 1];
                float ddz = rz - kp_s[3 * k + 2];
                float d = sqrtf(ddx * ddx + ddy * ddy + ddz * ddz);
                wsT[warp][k][idx] = __float2half_rn(fmaxf(1.0f - d * 25.0f, 0.0f));
            }
        }
        nbcnt += __popc(mask);
    }
    if (nbcnt > TOTC) nbcnt = TOTC;
    __syncwarp();

    int ktiles = (nbcnt + 15) >> 4;
    if (ktiles < 1) ktiles = 1;

    int r  = lane >> 2;       // fragment row group
    int tc = lane & 3;        // fragment col group

    float acc[8][4];
    #pragma unroll
    for (int ni = 0; ni < 8; ni++)
        #pragma unroll
        for (int j = 0; j < 4; j++) acc[ni][j] = 0.0f;

    for (int kt = 0; kt < ktiles; kt++) {
        // stage f tile: fsT[ch][j] for 16 neighbors (pad -> self, w=0 kills it)
        #pragma unroll
        for (int hc = 0; hc < 2; hc++) {
            int ch = lane + 32 * hc;
            float v[16];
            #pragma unroll
            for (int j = 0; j < 16; j++) {
                int p = kt * 16 + j;
                int idx = (p < nbcnt) ? nbr[warp][p] : m;
                v[j] = feats[(size_t)idx * CIN + ch];
            }
            __half2* frow = (__half2*)&fsT[warp][ch][0];
            #pragma unroll
            for (int j2 = 0; j2 < 8; j2++)
                frow[j2] = __floats2half2_rn(v[2 * j2], v[2 * j2 + 1]);
        }
        __syncwarp();

        int kb = kt * 16;
        uint32_t a0 = *(const uint32_t*)&wsT[warp][r][kb + 2 * tc];
        uint32_t a1 = *(const uint32_t*)&wsT[warp][r + 8][kb + 2 * tc];
        uint32_t a2 = *(const uint32_t*)&wsT[warp][r][kb + 2 * tc + 8];
        uint32_t a3 = *(const uint32_t*)&wsT[warp][r + 8][kb + 2 * tc + 8];
        #pragma unroll
        for (int ni = 0; ni < 8; ni++) {
            int n0 = ni * 8 + r;
            uint32_t b0 = *(const uint32_t*)&fsT[warp][n0][2 * tc];
            uint32_t b1 = *(const uint32_t*)&fsT[warp][n0][2 * tc + 8];
            asm volatile(
                "mma.sync.aligned.m16n8k16.row.col.f32.f16.f16.f32 "
                "{%0,%1,%2,%3}, {%4,%5,%6,%7}, {%8,%9}, {%0,%1,%2,%3};"
                : "+f"(acc[ni][0]), "+f"(acc[ni][1]), "+f"(acc[ni][2]), "+f"(acc[ni][3])
                : "r"(a0), "r"(a1), "r"(a2), "r"(a3), "r"(b0), "r"(b1));
        }
        __syncwarp();
    }

    // ---- epilogue: D[kp][ch] -> g_wfh[m][kp*64+ch] ------------------------
    __half2* dst = (__half2*)(g_wfh + (size_t)m * KC);
    #pragma unroll
    for (int ni = 0; ni < 8; ni++) {
        int c = ni * 8 + 2 * tc;
        dst[(r * 64 + c) >> 1] = __floats2half2_rn(acc[ni][0], acc[ni][1]);
        if (r < 7)
            dst[((r + 8) * 64 + c) >> 1] = __floats2half2_rn(acc[ni][2], acc[ni][3]);
    }
}

// -------------------- 3. W -> W^T fp16 [128][960] --------------------------
__global__ void __launch_bounds__(256) wt_kernel(const float* __restrict__ W)
{
    int i = blockIdx.x * 256 + threadIdx.x;
    int n = i / KC, k = i - n * KC;
    g_bwT[i] = __float2half_rn(W[k * COUT + n]);
}

// -------------------- 4. fp16 mma GEMM + fused BN partials -----------------
#define PH       40
#define TILE_B   (128 * PH * 2)
#define BUF_B    (2 * TILE_B)
#define SHP      132
#define GEMM_SMEM (2 * BUF_B)

__device__ __forceinline__ void issue_chunk(uint32_t buf, const __half* __restrict__ Ag,
                                            int c, int t)
{
    #pragma unroll
    for (int i = 0; i < 2; i++) {
        int id = i * 256 + t;
        int row = id >> 2, s16 = id & 3;
        CP_ASYNC16(buf + row * (PH * 2) + s16 * 16,
                   Ag + (size_t)row * KC + c * 32 + s16 * 8);
    }
    #pragma unroll
    for (int i = 0; i < 2; i++) {
        int id = i * 256 + t;
        int row = id >> 2, s16 = id & 3;
        CP_ASYNC16(buf + TILE_B + row * (PH * 2) + s16 * 16,
                   g_bwT + (size_t)row * KC + c * 32 + s16 * 8);
    }
    CP_COMMIT();
}

extern "C" __global__ void __launch_bounds__(256, 2) gemm_mma_kernel()
{
    extern __shared__ char smem[];
    int t = threadIdx.x, wid = t >> 5, lane = t & 31;
    int wr = (wid >> 1) * 32;
    int wc = (wid & 1) * 64;
    int lr = lane >> 2, lc = lane & 3;

    const __half* Ag = g_wfh + (size_t)blockIdx.x * 128 * KC;

    float acc[2][8][4];
    #pragma unroll
    for (int mi = 0; mi < 2; mi++)
        #pragma unroll
        for (int ni = 0; ni < 8; ni++)
            #pragma unroll
            for (int j = 0; j < 4; j++) acc[mi][ni][j] = 0.0f;

    uint32_t sb = smem_u32(smem);
    issue_chunk(sb, Ag, 0, t);

    for (int c = 0; c < 30; c++) {
        int b = c & 1;
        if (c + 1 < 30) issue_chunk(sb + (1 - b) * BUF_B, Ag, c + 1, t);
        if (c + 1 < 30) { CP_WAIT(1); } else { CP_WAIT(0); }
        __syncthreads();

        const char* As = smem + b * BUF_B;
        const char* Bs = smem + b * BUF_B + TILE_B;

        #pragma unroll
        for (int ks = 0; ks < 2; ks++) {
            int kb = ks * 16;
            uint32_t a[2][4];
            #pragma unroll
            for (int mi = 0; mi < 2; mi++) {
                int r0 = wr + mi * 16 + lr;
                a[mi][0] = *(const uint32_t*)(As + r0 * (PH * 2)       + (kb + 2 * lc) * 2);
                a[mi][1] = *(const uint32_t*)(As + (r0 + 8) * (PH * 2) + (kb + 2 * lc) * 2);
                a[mi][2] = *(const uint32_t*)(As + r0 * (PH * 2)       + (kb + 8 + 2 * lc) * 2);
                a[mi][3] = *(const uint32_t*)(As + (r0 + 8) * (PH * 2) + (kb + 8 + 2 * lc) * 2);
            }
            uint32_t bf[8][2];
            #pragma unroll
            for (int ni = 0; ni < 8; ni++) {
                int n0 = wc + ni * 8 + lr;
                bf[ni][0] = *(const uint32_t*)(Bs + n0 * (PH * 2) + (kb + 2 * lc) * 2);
                bf[ni][1] = *(const uint32_t*)(Bs + n0 * (PH * 2) + (kb + 8 + 2 * lc) * 2);
            }
            #pragma unroll
            for (int mi = 0; mi < 2; mi++)
                #pragma unroll
                for (int ni = 0; ni < 8; ni++)
                    asm volatile(
                        "mma.sync.aligned.m16n8k16.row.col.f32.f16.f16.f32 "
                        "{%0,%1,%2,%3}, {%4,%5,%6,%7}, {%8,%9}, {%0,%1,%2,%3};"
                        : "+f"(acc[mi][ni][0]), "+f"(acc[mi][ni][1]),
                          "+f"(acc[mi][ni][2]), "+f"(acc[mi][ni][3])
                        : "r"(a[mi][0]), "r"(a[mi][1]), "r"(a[mi][2]), "r"(a[mi][3]),
                          "r"(bf[ni][0]), "r"(bf[ni][1]));
        }
        __syncthreads();
    }

    // ---- two-pass epilogue: g_o + BN partials -----------------------------
    float* sh = (float*)smem;
    #pragma unroll
    for (int h = 0; h < 2; h++) {
        __syncthreads();
        if ((wid >> 2) == h) {
            #pragma unroll
            for (int mi = 0; mi < 2; mi++) {
                #pragma unroll
                for (int ni = 0; ni < 8; ni++) {
                    int r0 = wr + mi * 16 + lr - h * 64;
                    int cc = wc + ni * 8 + 2 * lc;
                    *(float2*)&sh[r0 * SHP + cc]       = make_float2(acc[mi][ni][0], acc[mi][ni][1]);
                    *(float2*)&sh[(r0 + 8) * SHP + cc] = make_float2(acc[mi][ni][2], acc[mi][ni][3]);
                }
            }
        }
        __syncthreads();

        float* op = g_o + ((size_t)blockIdx.x * 128 + h * 64) * COUT;
        #pragma unroll
        for (int it = 0; it < 8; it++) {
            int id = it * 256 + t;
            int row = id >> 5, c4 = id & 31;
            ((float4*)op)[id] = *(const float4*)&sh[row * SHP + c4 * 4];
        }

        int cch = t & 127, sub = t >> 7;
        float s = 0.0f, q = 0.0f;
        #pragma unroll 8
        for (int rr = sub * 32; rr < sub * 32 + 32; rr++) {
            float v = sh[rr * SHP + cch];
            s += v;
            q = fmaf(v, v, q);
        }
        g_ps[((size_t)blockIdx.x * 4 + h * 2 + sub) * COUT + cch] = s;
        g_pq[((size_t)blockIdx.x * 4 + h * 2 + sub) * COUT + cch] = q;
    }
}

// -------------------- 5. BN reduce (2-stage) -------------------------------
__global__ void __launch_bounds__(128) bn_mid_kernel()
{
    int c = threadIdx.x, bi = blockIdx.x;     // 32 blocks, 32 rows each
    float s = 0.0f, q = 0.0f;
    #pragma unroll 8
    for (int r = 0; r < 32; r++) {
        int row = bi * 32 + r;
        s += g_ps[row * COUT + c];
        q += g_pq[row * COUT + c];
    }
    g_ps2[bi * COUT + c] = s;
    g_pq2[bi * COUT + c] = q;
}

__global__ void __launch_bounds__(128) bn_final_kernel(const float* __restrict__ gamma,
                                                       const float* __restrict__ beta)
{
    int c = threadIdx.x;
    float s = 0.0f, q = 0.0f;
    #pragma unroll
    for (int b = 0; b < 32; b++) {
        s += g_ps2[b * COUT + c];
        q += g_pq2[b * COUT + c];
    }
    const float inv = 1.0f / (float)MTOT;
    float mu  = s * inv;
    float var = q * inv - mu * mu;
    float sc  = gamma[c] * rsqrtf(var + 1e-5f);
    g_scale[c] = sc;
    g_bias[c]  = beta[c] - mu * sc;
}

// -------------------- 6. apply BN + LeakyReLU ------------------------------
__global__ void __launch_bounds__(256) bn_apply_kernel(float* __restrict__ out)
{
    int i4 = blockIdx.x * 256 + threadIdx.x;
    int cb = (i4 & 31) * 4;
    float4 v = ((const float4*)g_o)[i4];
    float4 sc = *(const float4*)&g_scale[cb];
    float4 bs = *(const float4*)&g_bias[cb];
    float4 rr;
    rr.x = v.x * sc.x + bs.x;  rr.x = (rr.x >= 0.0f) ? rr.x : 0.2f * rr.x;
    rr.y = v.y * sc.y + bs.y;  rr.y = (rr.y >= 0.0f) ? rr.y : 0.2f * rr.y;
    rr.z = v.z * sc.z + bs.z;  rr.z = (rr.z >= 0.0f) ? rr.z : 0.2f * rr.z;
    rr.w = v.w * sc.w + bs.w;  rr.w = (rr.w >= 0.0f) ? rr.w : 0.2f * rr.w;
    ((float4*)out)[i4] = rr;
}

// -------------------- launch -----------------------------------------------
extern "C" void kernel_launch(void* const* d_in, const int* in_sizes, int n_in,
                              void* d_out, int out_size)
{
    const float* xyz    = (const float*)d_in[0];
    const float* feats  = (const float*)d_in[1];
    const float* kpts   = (const float*)d_in[2];
    const float* weight = (const float*)d_in[3];
    const float* gamma  = (const float*)d_in[4];
    const float* beta   = (const float*)d_in[5];
    float*       out    = (float*)d_out;
    (void)in_sizes; (void)n_in; (void)out_size;

    cudaFuncSetAttribute(gemm_mma_kernel, cudaFuncAttributeMaxDynamicSharedMemorySize, GEMM_SMEM);

    zero_cnt_kernel<<<8, 1024>>>();
    scatter_kernel<<<32, 1024>>>(xyz);
    sortb_kernel<<<32, 256>>>();
    wf_fused_kernel<<<MTOT / 4, 128>>>(xyz, feats, kpts);
    wt_kernel<<<480, 256>>>(weight);
    gemm_mma_kernel<<<MTOT / 128, 256, GEMM_SMEM>>>();
    bn_mid_kernel<<<32, 128>>>();
    bn_final_kernel<<<1, 128>>>(gamma, beta);
    bn_apply_kernel<<<(MTOT * COUT) / 1024, 256>>>(out);
}